// round 17
// baseline (speedup 1.0000x reference)
#include <cuda_runtime.h>

#define SLICES 32
#define NCH 32            // 8 batches * {img,img_t} * {g,b}
#define NBIN 256

__device__ float g_pa[NCH][SLICES][NBIN];   // per-CTA sig0 partials
__device__ float g_pb[NCH][SLICES][NBIN];   // per-CTA fused 4096*N + sig(+1) partials
__device__ float g_T[NCH][NBIN];            // final per-channel threshold sums
__device__ int   g_sync[8];                 // per-batch arrival counters (self-resetting)

__device__ __forceinline__ float frcp(float x) {
    float y; asm("rcp.approx.f32 %0, %1;" : "=f"(y) : "f"(x)); return y;
}

#define E_P1 12.182493960703473f       // e^2.5

// sig(2.5f) linear model over f~U[0,1): mean A0, slope b0
#define A0_SIG 0.754354f
#define INV_B0 2.337788f               // 1 / 0.427755

// linear-fit tail compensation: sig(2.5(f-d)) ~= A + B*(f-1/2);  B_d = B_{1-d}
#define A_M1 0.9711630f    // mean of sig(2.5(f+1))      (d=-1)
#define ET2  0.0288370f    // mean of sig(2.5(f-2))      (d=+2)
#define ET3  0.0024650f    // mean of sig(2.5(f-3)); also deficiency at d=-2
#define ET4  0.0002030f    // mean of sig(2.5(f-4)); also deficiency at d=-3
#define B1   0.0639120f    // slope for d=-1 and d=+2
#define B2   0.0056371f    // slope for d=-2 and d=+3
#define B3   0.0004640f    // slope for d=-3 and d=+4

__device__ __forceinline__ void process_pixel(float x, float* s_a, float* s_b) {
    float u = x * 255.0f;
    int k = (int)u;                    // x < 1 -> k <= 254, f in [0,1)
    float f = u - (float)k;
    float e0 = __expf(-2.5f * f);      // e^{-2.5 f}

    atomicAdd(&s_a[k], frcp(1.0f + e0));                    // d=0 -> threshold k
    atomicAdd(&s_b[k], 4096.0f + frcp(1.0f + e0 * E_P1));   // count + d=+1 -> threshold k+1
}

__global__ __launch_bounds__(256) void hist_kernel(const float* __restrict__ img,
                                                   const float* __restrict__ img_t) {
    __shared__ float s_a[NBIN];
    __shared__ float s_b[NBIN];
    int t = threadIdx.x;
    s_a[t] = 0.0f;
    s_b[t] = 0.0f;
    __syncthreads();

    int cidx = blockIdx.y;                 // 0..31  (= b*4 + im*2 + ch)
    int slice = blockIdx.x;                // 0..SLICES-1
    int b  = cidx >> 2;
    int im = (cidx >> 1) & 1;
    int ch = cidx & 1;                     // 0 -> g(plane 1), 1 -> b(plane 2)
    const float* src = im ? img_t : img;
    const float4* plane = (const float4*)(src + (size_t)(b * 3 + 1 + ch) * 65536);

    int base = slice * 512;
    #pragma unroll
    for (int v = 0; v < 2; v++) {
        float4 p = plane[base + v * 256 + t];
        process_pixel(p.x, s_a, s_b);
        process_pixel(p.y, s_a, s_b);
        process_pixel(p.z, s_a, s_b);
        process_pixel(p.w, s_a, s_b);
    }
    __syncthreads();

    g_pa[cidx][slice][t] = s_a[t];
    g_pb[cidx][slice][t] = s_b[t];
}

// 32 CTAs, one per channel: merge partials, decode, tail-compensate, suffix-scan,
// store T. The last CTA to finish in each batch computes the batch's loss.
__global__ __launch_bounds__(256) void mid_kernel(float* __restrict__ out) {
    int c = blockIdx.x;         // channel 0..31
    int t = threadIdx.x;        // bin / threshold 0..255
    int lane = t & 31;
    int wid = t >> 5;

    __shared__ float sLow[NBIN];
    __shared__ float sN[NBIN];
    __shared__ float sD[NBIN];
    __shared__ float sH[NBIN];
    __shared__ float scs[NBIN];
    __shared__ float wtot[8];
    __shared__ int   isLast;

    // merge 32 slices of both arrays (64 independent loads, high MLP)
    float a0 = 0.f, a1 = 0.f, a2 = 0.f, a3 = 0.f;
    float b0 = 0.f, b1 = 0.f, b2 = 0.f, b3 = 0.f;
    #pragma unroll
    for (int sl = 0; sl < SLICES; sl += 4) {
        a0 += g_pa[c][sl + 0][t];
        a1 += g_pa[c][sl + 1][t];
        a2 += g_pa[c][sl + 2][t];
        a3 += g_pa[c][sl + 3][t];
        b0 += g_pb[c][sl + 0][t];
        b1 += g_pb[c][sl + 1][t];
        b2 += g_pb[c][sl + 2][t];
        b3 += g_pb[c][sl + 3][t];
    }
    float a = (a0 + a1) + (a2 + a3);
    float v = (b0 + b1) + (b2 + b3);           // 4096*N + sig1-sum (low < 4096)
    float N = floorf(v * (1.0f / 4096.0f));
    sN[t]   = N;
    sLow[t] = v - 4096.0f * N;                 // sum sig1 of bin t
    sD[t]   = (a - A0_SIG * N) * INV_B0;       // estimated sum(f - 1/2)
    sH[t]   = a;                               // sig0 part
    __syncthreads();

    // window reconstruction + tail compensation
    float acc = sH[t];
    if (t >= 1) acc += sLow[t - 1];
    #define ACC(IDX, A, B) { int _i = (IDX); if (_i >= 0 && _i < NBIN) \
        acc += (A) * sN[_i] + (B) * sD[_i]; }
    ACC(t + 1,  A_M1, B1)    // d=-1
    ACC(t - 2,  ET2,  B1)    // d=+2
    ACC(t + 2, -ET3,  B2)    // d=-2 (deficiency vs suffix 1.0)
    ACC(t - 3,  ET3,  B2)    // d=+3
    ACC(t + 3, -ET4,  B3)    // d=-3 (deficiency)
    ACC(t - 4,  ET4,  B3)    // d=+4
    #undef ACC

    // inclusive suffix scan of counts via warp shuffles
    {
        float sv = sN[t];
        #pragma unroll
        for (int off = 1; off < 32; off <<= 1) {
            float w = __shfl_down_sync(0xFFFFFFFFu, sv, off);
            if (lane + off < 32) sv += w;
        }
        if (lane == 0) wtot[wid] = sv;
        scs[t] = sv;
    }
    __syncthreads();
    {
        float add = 0.f;
        for (int w = wid + 1; w < 8; w++) add += wtot[w];
        scs[t] += add;
    }
    __syncthreads();

    // final threshold sum: window + tails + (# pixels with bin >= t+2)
    float T = acc + ((t + 2 < NBIN) ? scs[t + 2] : 0.0f);
    g_T[c][t] = T;

    // arrival counter (release): partial T stores must be visible first
    __threadfence();
    if (t == 0) {
        int old = atomicAdd(&g_sync[c >> 2], 1);
        isLast = (old == 3);
    }
    __syncthreads();
    if (!isLast) return;
    __threadfence();   // acquire side: order subsequent g_T reads

    // this CTA is the 4th of its batch: compute the batch loss
    int b4 = (c >> 2) << 2;
    float hgx = g_T[b4 + 0][0];
    float hgy = g_T[b4 + 2][0];
    float hbx = g_T[b4 + 1][0];
    float hby = g_T[b4 + 3][0];
    float term = 0.0f;
    if (t < 255) {
        float dg = (hgx - g_T[b4 + 0][t + 1]) - (hgy - g_T[b4 + 2][t + 1]);
        float db = (hbx - g_T[b4 + 1][t + 1]) - (hby - g_T[b4 + 3][t + 1]);
        term = dg * dg + db * db;
    }
    #pragma unroll
    for (int off = 16; off > 0; off >>= 1)
        term += __shfl_down_sync(0xFFFFFFFFu, term, off);
    if (lane == 0) wtot[wid] = term;
    __syncthreads();
    if (wid == 0) {
        float s = (lane < 8) ? wtot[lane] : 0.0f;
        #pragma unroll
        for (int off = 4; off > 0; off >>= 1)
            s += __shfl_down_sync(0xFFFFFFFFu, s, off);
        if (lane == 0) {
            out[c >> 2] = s * (1.0f / (65536.0f * 65536.0f));
            g_sync[c >> 2] = 0;   // reset for next graph replay
        }
    }
}

extern "C" void kernel_launch(void* const* d_in, const int* in_sizes, int n_in,
                              void* d_out, int out_size) {
    const float* img   = (const float*)d_in[0];
    const float* img_t = (const float*)d_in[1];
    float* out = (float*)d_out;

    dim3 grid(SLICES, NCH);
    hist_kernel<<<grid, 256>>>(img, img_t);
    mid_kernel<<<NCH, 256>>>(out);
}